// round 16
// baseline (speedup 1.0000x reference)
#include <cuda_runtime.h>
#include <cuda_fp16.h>
#include <math.h>
#include <stdint.h>

#define BATCH 16
#define CHAN 512
#define HW 1024
#define O3 1536
#define HEADS 4
#define DHEAD 128
#define SEQ 1024
#define SCALE 0.08838834764831845f   // 128^-0.5

// fp16 staging of inputs for the QKV GEMM
__device__ __half g_Wh[O3 * CHAN];            // [o][c]
__device__ __half g_Fh[BATCH * HW * CHAN];    // [b][p][c]  (fmap transposed)

// Scratch (fp16): Q (scale folded), K (emb folded) [b,h,seq,d]; V transposed [b,h,d,seq]
__device__ __half g_Q[BATCH * HEADS * SEQ * DHEAD];
__device__ __half g_K[BATCH * HEADS * SEQ * DHEAD];
__device__ __half g_Vt[BATCH * HEADS * DHEAD * SEQ];

// ---------------------------------------------------------------------------
// helpers
// ---------------------------------------------------------------------------
__device__ __forceinline__ void mma16(float* c, const unsigned* a, const unsigned* b) {
    asm volatile(
        "mma.sync.aligned.m16n8k16.row.col.f32.f16.f16.f32 "
        "{%0,%1,%2,%3}, {%4,%5,%6,%7}, {%8,%9}, {%0,%1,%2,%3};\n"
        : "+f"(c[0]), "+f"(c[1]), "+f"(c[2]), "+f"(c[3])
        : "r"(a[0]), "r"(a[1]), "r"(a[2]), "r"(a[3]), "r"(b[0]), "r"(b[1]));
}
__device__ __forceinline__ uint32_t smem_u32(const void* p) {
    uint32_t a;
    asm("{ .reg .u64 t; cvta.to.shared.u64 t, %1; cvt.u32.u64 %0, t; }" : "=r"(a) : "l"(p));
    return a;
}
#define CP_ASYNC16(dst, src) \
    asm volatile("cp.async.cg.shared.global [%0], [%1], 16;" :: "r"(dst), "l"(src))
#define CP_COMMIT() asm volatile("cp.async.commit_group;" ::: "memory")
#define CP_WAIT1()  asm volatile("cp.async.wait_group 1;" ::: "memory")
#define CP_WAIT0()  asm volatile("cp.async.wait_group 0;" ::: "memory")
#define U32H(p) (*(const unsigned*)(p))

// ---------------------------------------------------------------------------
// Prep kernel A: w_qkv fp32 -> g_Wh fp16
// ---------------------------------------------------------------------------
__global__ __launch_bounds__(256) void conv_w_kernel(const float* __restrict__ w) {
    const int i = blockIdx.x * 256 + threadIdx.x;
    float4 v = ((const float4*)w)[i];
    ((__half2*)g_Wh)[i * 2]     = __floats2half2_rn(v.x, v.y);
    ((__half2*)g_Wh)[i * 2 + 1] = __floats2half2_rn(v.z, v.w);
}

// ---------------------------------------------------------------------------
// Prep kernel B: fmap [b][c][p] fp32 -> g_Fh [b][p][c] fp16
// ---------------------------------------------------------------------------
__global__ __launch_bounds__(256) void transp_f_kernel(const float* __restrict__ fmap) {
    __shared__ float ts[32][33];
    const int b = blockIdx.z, c0 = blockIdx.y * 32, p0 = blockIdx.x * 32;
    const int tx = threadIdx.x & 31, ty = threadIdx.x >> 5;
    const float* src = fmap + ((size_t)b * CHAN + c0) * HW + p0;
#pragma unroll
    for (int i = 0; i < 4; i++)
        ts[ty + i * 8][tx] = src[(size_t)(ty + i * 8) * HW + tx];
    __syncthreads();
    __half* dst = g_Fh + ((size_t)b * HW + p0) * CHAN + c0;
#pragma unroll
    for (int i = 0; i < 4; i++)
        dst[(size_t)(ty + i * 8) * CHAN + tx] = __float2half(ts[tx][ty + i * 8]);
}

// ---------------------------------------------------------------------------
// Kernel 1: QKV projection GEMM, fp16 mma m16n8k16, 2 CTAs/SM (R15 winner).
// CTA tile 128(o) x 128(p) x 64(k), 8 stages; warp tile 64x32 (2x4 warps).
// ---------------------------------------------------------------------------
#define WSH 72
#define FSH 72
#define QW0 0
#define QW1 (128 * WSH)
#define QF0 (2 * 128 * WSH)
#define QF1 (QF0 + 128 * FSH)
#define CSS 133
#define K1_SMEM ((QF1 + 128 * FSH) * 2)   // 73728 B

__global__ __launch_bounds__(256, 2) void qkv_mma_kernel(
    const float* __restrict__ height, const float* __restrict__ width)
{
    extern __shared__ __half sh1[];
    const uint32_t smb = smem_u32(sh1);

    const int b  = blockIdx.z;
    const int o0 = blockIdx.y * 128;
    const int p0 = blockIdx.x * 128;
    const int tid = threadIdx.x;
    const int warp = tid >> 5, lane = tid & 31;
    const int g = lane >> 2, t = lane & 3;
    const int wm = warp >> 2, wn = warp & 3;

    const __half* Fb = g_Fh + (size_t)b * HW * CHAN;

#define QKV_STAGE(ci) do {                                                         \
        const int _k0 = (ci) * 64;                                                 \
        const uint32_t _wb = smb + (((ci) & 1) ? QW1 : QW0) * 2;                   \
        const uint32_t _fb = smb + (((ci) & 1) ? QF1 : QF0) * 2;                   \
        _Pragma("unroll")                                                          \
        for (int pass = 0; pass < 4; pass++) {                                     \
            const int id = tid + pass * 256;                                       \
            const int wr = id >> 3, wc8 = (id & 7) * 8;                            \
            CP_ASYNC16(_wb + (uint32_t)(wr * WSH + wc8) * 2,                       \
                       g_Wh + (size_t)(o0 + wr) * CHAN + _k0 + wc8);               \
            CP_ASYNC16(_fb + (uint32_t)(wr * FSH + wc8) * 2,                       \
                       Fb + (size_t)(p0 + wr) * CHAN + _k0 + wc8);                 \
        }                                                                          \
        CP_COMMIT();                                                               \
    } while (0)

    float c[4][4][4];
#pragma unroll
    for (int mt = 0; mt < 4; mt++)
#pragma unroll
        for (int nt = 0; nt < 4; nt++)
#pragma unroll
            for (int i = 0; i < 4; i++) c[mt][nt][i] = 0.0f;

    QKV_STAGE(0);

    for (int ci = 0; ci < 8; ci++) {
        if (ci < 7) QKV_STAGE(ci + 1);
        if (ci < 7) { CP_WAIT1(); } else { CP_WAIT0(); }
        __syncthreads();

        const __half* Ws = sh1 + ((ci & 1) ? QW1 : QW0);
        const __half* Fs = sh1 + ((ci & 1) ? QF1 : QF0);

#pragma unroll
        for (int ks = 0; ks < 4; ks++) {
            const int kc = ks * 16;
            unsigned af[4][4], bf[4][2];
#pragma unroll
            for (int mt = 0; mt < 4; mt++) {
                const int mb = wm * 64 + mt * 16;
                af[mt][0] = U32H(&Ws[(mb + g) * WSH + kc + 2 * t]);
                af[mt][1] = U32H(&Ws[(mb + 8 + g) * WSH + kc + 2 * t]);
                af[mt][2] = U32H(&Ws[(mb + g) * WSH + kc + 2 * t + 8]);
                af[mt][3] = U32H(&Ws[(mb + 8 + g) * WSH + kc + 2 * t + 8]);
            }
#pragma unroll
            for (int nt = 0; nt < 4; nt++) {
                const int nn = wn * 32 + nt * 8 + g;
                bf[nt][0] = U32H(&Fs[nn * FSH + kc + 2 * t]);
                bf[nt][1] = U32H(&Fs[nn * FSH + kc + 2 * t + 8]);
            }
#pragma unroll
            for (int mt = 0; mt < 4; mt++)
#pragma unroll
                for (int nt = 0; nt < 4; nt++)
                    mma16(c[mt][nt], af[mt], bf[nt]);
        }
        __syncthreads();
    }

    // Epilogue: stage C (128 o x 128 p) to smem, then emit fp16 Q/K/Vt
    float* Cs = (float*)sh1;   // 128 x CSS
#pragma unroll
    for (int mt = 0; mt < 4; mt++)
#pragma unroll
        for (int nt = 0; nt < 4; nt++) {
            const int m = wm * 64 + mt * 16 + g;
            const int n = wn * 32 + nt * 8 + 2 * t;
            Cs[m * CSS + n]           = c[mt][nt][0];
            Cs[m * CSS + n + 1]       = c[mt][nt][1];
            Cs[(m + 8) * CSS + n]     = c[mt][nt][2];
            Cs[(m + 8) * CSS + n + 1] = c[mt][nt][3];
        }
    __syncthreads();

    const int part = o0 >> 9;            // 0=q 1=k 2=v
    const int head = (o0 >> 7) & 3;

    if (part == 2) {
#pragma unroll 2
        for (int it = 0; it < 16; it++) {
            const int d = warp + it * 8;
            __half* vr = g_Vt + ((size_t)(b * HEADS + head) * DHEAD + d) * SEQ + p0;
#pragma unroll
            for (int pc = 0; pc < 4; pc++) {
                const int pl = pc * 32 + lane;
                vr[pl] = __float2half(Cs[d * CSS + pl]);
            }
        }
        return;
    }

#pragma unroll 2
    for (int it = 0; it < 16; it++) {
        const int pl = warp + it * 8;
        const int p  = p0 + pl;
        const int xh = p >> 5, yw = p & 31;
        const size_t ob = ((size_t)(b * HEADS + head) * SEQ + p) * DHEAD;
        if (part == 0) {
#pragma unroll
            for (int dc = 0; dc < 4; dc++) {
                const int d = dc * 32 + lane;
                g_Q[ob + d] = __float2half(Cs[d * CSS + pl] * SCALE);
            }
        } else {
#pragma unroll
            for (int dc = 0; dc < 4; dc++) {
                const int d = dc * 32 + lane;
                g_K[ob + d] = __float2half(Cs[d * CSS + pl]
                                           + height[xh * DHEAD + d] + width[yw * DHEAD + d]);
            }
        }
    }
}

// ---------------------------------------------------------------------------
// Kernel 2: flash attention, fp16 mma, 256 threads, 2 CTAs/SM.
// Br=64, Bc=64, 16 j-tiles. No running max.
// S-phase ks-outer/nt-inner: 4 INDEPENDENT accumulator chains per warp
// (chain depth 8 -> pipelined; covers HMMA latency at 4 warps/SMSP).
// PV-phase: warp = (row-group 0..1) x (d-quarter 0..3): 32 rows x 32 d.
// Strides: K 136, Vt/P 72 (bank = 4g+t+const, conflict-free).
// ---------------------------------------------------------------------------
#define KSH 136
#define VSH 72
#define PSH 72
#define KS0_H 0
#define KS1_H (64 * KSH)
#define VS0_H (2 * 64 * KSH)
#define VS1_H (VS0_H + 128 * VSH)
#define PS_H  (VS1_H + 128 * VSH)
#define LB_B  ((PS_H + 64 * PSH) * 2)    // 80896
#define K2_SMEM (LB_B + 512)             // 81408 B -> 2 CTAs/SM

__global__ __launch_bounds__(256, 2) void attn_mma_kernel(float* __restrict__ out)
{
    extern __shared__ __half smh[];
    const uint32_t smb = smem_u32(smh);
    __half* Ph = smh + PS_H;   // 64 x PSH (CTA-shared)

    const int bh = blockIdx.y;
    const int i0 = blockIdx.x * 64;
    const int tid = threadIdx.x;
    const int warp = tid >> 5, lane = tid & 31;
    const int g = lane >> 2, t = lane & 3;

    const int rw  = warp >> 1;         // S row group (16 rows)
    const int chs = warp & 1;          // S col half (32 cols)
    const int rg  = warp >> 2;         // PV row group (32 rows)
    const int dq  = warp & 3;          // PV d quarter (32 d)
    const int r0 = rg * 32;
    const int dbase = dq * 32;

    const size_t base  = (size_t)bh * SEQ * DHEAD;
    const size_t vbase = (size_t)bh * DHEAD * SEQ;

#define ATTN_STAGE(jn) do {                                                        \
        const uint32_t _kb = smb + (((jn) & 1) ? KS1_H : KS0_H) * 2;               \
        const uint32_t _vb = smb + (((jn) & 1) ? VS1_H : VS0_H) * 2;               \
        const __half* _Kg = g_K + base + (size_t)((jn) * 64) * DHEAD;              \
        const __half* _Vg = g_Vt + vbase + (size_t)((jn) * 64);                    \
        _Pragma("unroll")                                                          \
        for (int pass = 0; pass < 4; pass++) {                                     \
            const int id = tid + pass * 256;                                       \
            const int kr = id >> 4, kc8 = (id & 15) * 8;                           \
            CP_ASYNC16(_kb + (uint32_t)(kr * KSH + kc8) * 2,                       \
                       _Kg + (size_t)kr * DHEAD + kc8);                            \
            const int vr = id >> 3, vc8 = (id & 7) * 8;                            \
            CP_ASYNC16(_vb + (uint32_t)(vr * VSH + vc8) * 2,                       \
                       _Vg + (size_t)vr * SEQ + vc8);                              \
        }                                                                          \
        CP_COMMIT();                                                               \
    } while (0)

    ATTN_STAGE(0);

    // Preload Q A-fragments (rows i0 + rw*16 .. +15), 8 k16-steps
    unsigned QA[8][4];
    {
        const __half* Qg = g_Q + base + (size_t)(i0 + rw * 16) * DHEAD;
#pragma unroll
        for (int ks = 0; ks < 8; ks++) {
            QA[ks][0] = U32H(&Qg[g * DHEAD + ks * 16 + 2 * t]);
            QA[ks][1] = U32H(&Qg[(g + 8) * DHEAD + ks * 16 + 2 * t]);
            QA[ks][2] = U32H(&Qg[g * DHEAD + ks * 16 + 2 * t + 8]);
            QA[ks][3] = U32H(&Qg[(g + 8) * DHEAD + ks * 16 + 2 * t + 8]);
        }
    }

    float l_a = 0.0f, l_b = 0.0f;
    float oc[2][4][4];
#pragma unroll
    for (int mt = 0; mt < 2; mt++)
#pragma unroll
        for (int dt = 0; dt < 4; dt++)
#pragma unroll
            for (int i = 0; i < 4; i++) oc[mt][dt][i] = 0.0f;

    for (int jt = 0; jt < 16; jt++) {
        if (jt < 15) ATTN_STAGE(jt + 1);
        if (jt < 15) { CP_WAIT1(); } else { CP_WAIT0(); }
        __syncthreads();

        const __half* Ks  = smh + ((jt & 1) ? KS1_H : KS0_H);
        const __half* Vth = smh + ((jt & 1) ? VS1_H : VS0_H);

        // S = Q @ K^T : ks-outer, 4 independent sc chains (warp tile 16 x 32)
        float sc[4][4];
#pragma unroll
        for (int nt = 0; nt < 4; nt++)
#pragma unroll
            for (int i = 0; i < 4; i++) sc[nt][i] = 0.0f;

#pragma unroll
        for (int ks = 0; ks < 8; ks++) {
            const int kc = ks * 16;
#pragma unroll
            for (int nt = 0; nt < 4; nt++) {
                const __half* Kr = &Ks[(chs * 32 + nt * 8 + g) * KSH];
                unsigned bf[2];
                bf[0] = U32H(&Kr[kc + 2 * t]);
                bf[1] = U32H(&Kr[kc + 2 * t + 8]);
                mma16(sc[nt], QA[ks], bf);
            }
        }

        // exp + partial sums + P store
#pragma unroll
        for (int nt = 0; nt < 4; nt++) {
            const float p0 = __expf(sc[nt][0]);
            const float p1 = __expf(sc[nt][1]);
            const float p2 = __expf(sc[nt][2]);
            const float p3 = __expf(sc[nt][3]);
            l_a += p0 + p1;
            l_b += p2 + p3;
            const int n2 = chs * 32 + nt * 8 + 2 * t;
            *(__half2*)&Ph[(rw * 16 + g) * PSH + n2]     = __floats2half2_rn(p0, p1);
            *(__half2*)&Ph[(rw * 16 + 8 + g) * PSH + n2] = __floats2half2_rn(p2, p3);
        }
        __syncthreads();   // P complete before cross-warp PV reads

        // O += P @ V : rows r0..r0+31, d = dbase..dbase+31; k = 64 (4 k16-steps)
#pragma unroll
        for (int ks = 0; ks < 4; ks++) {
            const int kc = ks * 16;
            unsigned a0[4], a1[4];
            a0[0] = U32H(&Ph[(r0 + g) * PSH + kc + 2 * t]);
            a0[1] = U32H(&Ph[(r0 + 8 + g) * PSH + kc + 2 * t]);
            a0[2] = U32H(&Ph[(r0 + g) * PSH + kc + 2 * t + 8]);
            a0[3] = U32H(&Ph[(r0 + 8 + g) * PSH + kc + 2 * t + 8]);
            a1[0] = U32H(&Ph[(r0 + 16 + g) * PSH + kc + 2 * t]);
            a1[1] = U32H(&Ph[(r0 + 24 + g) * PSH + kc + 2 * t]);
            a1[2] = U32H(&Ph[(r0 + 16 + g) * PSH + kc + 2 * t + 8]);
            a1[3] = U32H(&Ph[(r0 + 24 + g) * PSH + kc + 2 * t + 8]);
#pragma unroll
            for (int dt = 0; dt < 4; dt++) {
                unsigned bf[2];
                bf[0] = U32H(&Vth[(dbase + dt * 8 + g) * VSH + kc + 2 * t]);
                bf[1] = U32H(&Vth[(dbase + dt * 8 + g) * VSH + kc + 2 * t + 8]);
                mma16(oc[0][dt], a0, bf);
                mma16(oc[1][dt], a1, bf);
            }
        }
        __syncthreads();   // PV reads done before next tile's P writes / cp.async
    }

    // ---- epilogue ----
    l_a += __shfl_xor_sync(0xffffffffu, l_a, 1);
    l_a += __shfl_xor_sync(0xffffffffu, l_a, 2);
    l_b += __shfl_xor_sync(0xffffffffu, l_b, 1);
    l_b += __shfl_xor_sync(0xffffffffu, l_b, 2);
    float* lbuf = (float*)((char*)smh + LB_B);
    if (t == 0) {
        lbuf[chs * 64 + rw * 16 + g]     = l_a;
        lbuf[chs * 64 + rw * 16 + 8 + g] = l_b;
    }
    __syncthreads();

    float linv[2][2];
#pragma unroll
    for (int mt = 0; mt < 2; mt++) {
        const int ra = r0 + mt * 16 + g;
        linv[mt][0] = 1.0f / (lbuf[ra] + lbuf[64 + ra]);
        linv[mt][1] = 1.0f / (lbuf[ra + 8] + lbuf[64 + ra + 8]);
    }

    // stage O transposed [d][i_local]: 128 x 68 floats (disjoint from lbuf)
    float* Os = (float*)smh;
#pragma unroll
    for (int mt = 0; mt < 2; mt++)
#pragma unroll
        for (int dt = 0; dt < 4; dt++) {
            const int dr = dbase + dt * 8 + 2 * t;
            const int ra = r0 + mt * 16 + g;
            Os[dr * 68 + ra]           = oc[mt][dt][0] * linv[mt][0];
            Os[(dr + 1) * 68 + ra]     = oc[mt][dt][1] * linv[mt][0];
            Os[dr * 68 + ra + 8]       = oc[mt][dt][2] * linv[mt][1];
            Os[(dr + 1) * 68 + ra + 8] = oc[mt][dt][3] * linv[mt][1];
        }
    __syncthreads();

    // coalesced output: lanes 0-15 -> row d, lanes 16-31 -> row d+1 (256B each)
    const int b = bh >> 2, head = bh & 3;
#pragma unroll
    for (int it = 0; it < 8; it++) {
        const int d = warp * 2 + (lane >> 4) + it * 16;
        const int cl = (lane & 15) * 4;
        float4 v = *(const float4*)&Os[d * 68 + cl];
        *(float4*)&out[((size_t)(b * (HEADS * DHEAD) + head * DHEAD + d)) * HW + i0 + cl] = v;
    }
}

// ---------------------------------------------------------------------------
extern "C" void kernel_launch(void* const* d_in, const int* in_sizes, int n_in,
                              void* d_out, int out_size)
{
    const float* fmap   = (const float*)d_in[0];
    const float* w_qkv  = (const float*)d_in[1];
    const float* height = (const float*)d_in[2];
    const float* width  = (const float*)d_in[3];
    float* out = (float*)d_out;

    cudaFuncSetAttribute(qkv_mma_kernel,  cudaFuncAttributeMaxDynamicSharedMemorySize, K1_SMEM);
    cudaFuncSetAttribute(attn_mma_kernel, cudaFuncAttributeMaxDynamicSharedMemorySize, K2_SMEM);

    conv_w_kernel<<<O3 * CHAN / 1024, 256>>>(w_qkv);
    transp_f_kernel<<<dim3(HW / 32, CHAN / 32, BATCH), 256>>>(fmap);
    qkv_mma_kernel<<<dim3(HW / 128, O3 / 128, BATCH), 256, K1_SMEM>>>(height, width);
    attn_mma_kernel<<<dim3(SEQ / 64, BATCH * HEADS), 256, K2_SMEM>>>(out);
}

// round 17
// speedup vs baseline: 1.0704x; 1.0704x over previous
#include <cuda_runtime.h>
#include <cuda_fp16.h>
#include <math.h>
#include <stdint.h>

#define BATCH 16
#define CHAN 512
#define HW 1024
#define O3 1536
#define HEADS 4
#define DHEAD 128
#define SEQ 1024
#define SCALE 0.08838834764831845f   // 128^-0.5

// fp16 staging of inputs for the QKV GEMM
__device__ __half g_Wh[O3 * CHAN];            // [o][c]
__device__ __half g_Fh[BATCH * HW * CHAN];    // [b][p][c]  (fmap transposed)

// Scratch (fp16): Q (scale folded), K (emb folded) [b,h,seq,d]; V transposed [b,h,d,seq]
__device__ __half g_Q[BATCH * HEADS * SEQ * DHEAD];
__device__ __half g_K[BATCH * HEADS * SEQ * DHEAD];
__device__ __half g_Vt[BATCH * HEADS * DHEAD * SEQ];

// ---------------------------------------------------------------------------
// helpers
// ---------------------------------------------------------------------------
__device__ __forceinline__ void mma16(float* c, const unsigned* a, const unsigned* b) {
    asm volatile(
        "mma.sync.aligned.m16n8k16.row.col.f32.f16.f16.f32 "
        "{%0,%1,%2,%3}, {%4,%5,%6,%7}, {%8,%9}, {%0,%1,%2,%3};\n"
        : "+f"(c[0]), "+f"(c[1]), "+f"(c[2]), "+f"(c[3])
        : "r"(a[0]), "r"(a[1]), "r"(a[2]), "r"(a[3]), "r"(b[0]), "r"(b[1]));
}
__device__ __forceinline__ void ldsm4(unsigned& r0, unsigned& r1, unsigned& r2,
                                      unsigned& r3, uint32_t addr) {
    asm volatile("ldmatrix.sync.aligned.m8n8.x4.shared.b16 {%0,%1,%2,%3}, [%4];"
                 : "=r"(r0), "=r"(r1), "=r"(r2), "=r"(r3) : "r"(addr));
}
__device__ __forceinline__ uint32_t smem_u32(const void* p) {
    uint32_t a;
    asm("{ .reg .u64 t; cvta.to.shared.u64 t, %1; cvt.u32.u64 %0, t; }" : "=r"(a) : "l"(p));
    return a;
}
#define CP_ASYNC16(dst, src) \
    asm volatile("cp.async.cg.shared.global [%0], [%1], 16;" :: "r"(dst), "l"(src))
#define CP_COMMIT() asm volatile("cp.async.commit_group;" ::: "memory")
#define CP_WAIT1()  asm volatile("cp.async.wait_group 1;" ::: "memory")
#define CP_WAIT0()  asm volatile("cp.async.wait_group 0;" ::: "memory")
#define U32H(p) (*(const unsigned*)(p))

// ---------------------------------------------------------------------------
// Prep kernel A: w_qkv fp32 -> g_Wh fp16
// ---------------------------------------------------------------------------
__global__ __launch_bounds__(256) void conv_w_kernel(const float* __restrict__ w) {
    const int i = blockIdx.x * 256 + threadIdx.x;
    float4 v = ((const float4*)w)[i];
    ((__half2*)g_Wh)[i * 2]     = __floats2half2_rn(v.x, v.y);
    ((__half2*)g_Wh)[i * 2 + 1] = __floats2half2_rn(v.z, v.w);
}

// ---------------------------------------------------------------------------
// Prep kernel B: fmap [b][c][p] fp32 -> g_Fh [b][p][c] fp16
// ---------------------------------------------------------------------------
__global__ __launch_bounds__(256) void transp_f_kernel(const float* __restrict__ fmap) {
    __shared__ float ts[32][33];
    const int b = blockIdx.z, c0 = blockIdx.y * 32, p0 = blockIdx.x * 32;
    const int tx = threadIdx.x & 31, ty = threadIdx.x >> 5;
    const float* src = fmap + ((size_t)b * CHAN + c0) * HW + p0;
#pragma unroll
    for (int i = 0; i < 4; i++)
        ts[ty + i * 8][tx] = src[(size_t)(ty + i * 8) * HW + tx];
    __syncthreads();
    __half* dst = g_Fh + ((size_t)b * HW + p0) * CHAN + c0;
#pragma unroll
    for (int i = 0; i < 4; i++)
        dst[(size_t)(ty + i * 8) * CHAN + tx] = __float2half(ts[tx][ty + i * 8]);
}

// ---------------------------------------------------------------------------
// Kernel 1: QKV projection GEMM, fp16 mma m16n8k16, 2 CTAs/SM (R15 winner).
// CTA tile 128(o) x 128(p) x 64(k), 8 stages; warp tile 64x32 (2x4 warps).
// ---------------------------------------------------------------------------
#define WSH 72
#define FSH 72
#define QW0 0
#define QW1 (128 * WSH)
#define QF0 (2 * 128 * WSH)
#define QF1 (QF0 + 128 * FSH)
#define CSS 133
#define K1_SMEM ((QF1 + 128 * FSH) * 2)   // 73728 B

__global__ __launch_bounds__(256, 2) void qkv_mma_kernel(
    const float* __restrict__ height, const float* __restrict__ width)
{
    extern __shared__ __half sh1[];
    const uint32_t smb = smem_u32(sh1);

    const int b  = blockIdx.z;
    const int o0 = blockIdx.y * 128;
    const int p0 = blockIdx.x * 128;
    const int tid = threadIdx.x;
    const int warp = tid >> 5, lane = tid & 31;
    const int g = lane >> 2, t = lane & 3;
    const int wm = warp >> 2, wn = warp & 3;

    const __half* Fb = g_Fh + (size_t)b * HW * CHAN;

#define QKV_STAGE(ci) do {                                                         \
        const int _k0 = (ci) * 64;                                                 \
        const uint32_t _wb = smb + (((ci) & 1) ? QW1 : QW0) * 2;                   \
        const uint32_t _fb = smb + (((ci) & 1) ? QF1 : QF0) * 2;                   \
        _Pragma("unroll")                                                          \
        for (int pass = 0; pass < 4; pass++) {                                     \
            const int id = tid + pass * 256;                                       \
            const int wr = id >> 3, wc8 = (id & 7) * 8;                            \
            CP_ASYNC16(_wb + (uint32_t)(wr * WSH + wc8) * 2,                       \
                       g_Wh + (size_t)(o0 + wr) * CHAN + _k0 + wc8);               \
            CP_ASYNC16(_fb + (uint32_t)(wr * FSH + wc8) * 2,                       \
                       Fb + (size_t)(p0 + wr) * CHAN + _k0 + wc8);                 \
        }                                                                          \
        CP_COMMIT();                                                               \
    } while (0)

    float c[4][4][4];
#pragma unroll
    for (int mt = 0; mt < 4; mt++)
#pragma unroll
        for (int nt = 0; nt < 4; nt++)
#pragma unroll
            for (int i = 0; i < 4; i++) c[mt][nt][i] = 0.0f;

    QKV_STAGE(0);

    for (int ci = 0; ci < 8; ci++) {
        if (ci < 7) QKV_STAGE(ci + 1);
        if (ci < 7) { CP_WAIT1(); } else { CP_WAIT0(); }
        __syncthreads();

        const __half* Ws = sh1 + ((ci & 1) ? QW1 : QW0);
        const __half* Fs = sh1 + ((ci & 1) ? QF1 : QF0);

#pragma unroll
        for (int ks = 0; ks < 4; ks++) {
            const int kc = ks * 16;
            unsigned af[4][4], bf[4][2];
#pragma unroll
            for (int mt = 0; mt < 4; mt++) {
                const int mb = wm * 64 + mt * 16;
                af[mt][0] = U32H(&Ws[(mb + g) * WSH + kc + 2 * t]);
                af[mt][1] = U32H(&Ws[(mb + 8 + g) * WSH + kc + 2 * t]);
                af[mt][2] = U32H(&Ws[(mb + g) * WSH + kc + 2 * t + 8]);
                af[mt][3] = U32H(&Ws[(mb + 8 + g) * WSH + kc + 2 * t + 8]);
            }
#pragma unroll
            for (int nt = 0; nt < 4; nt++) {
                const int nn = wn * 32 + nt * 8 + g;
                bf[nt][0] = U32H(&Fs[nn * FSH + kc + 2 * t]);
                bf[nt][1] = U32H(&Fs[nn * FSH + kc + 2 * t + 8]);
            }
#pragma unroll
            for (int mt = 0; mt < 4; mt++)
#pragma unroll
                for (int nt = 0; nt < 4; nt++)
                    mma16(c[mt][nt], af[mt], bf[nt]);
        }
        __syncthreads();
    }

    // Epilogue: stage C (128 o x 128 p) to smem, then emit fp16 Q/K/Vt
    float* Cs = (float*)sh1;   // 128 x CSS
#pragma unroll
    for (int mt = 0; mt < 4; mt++)
#pragma unroll
        for (int nt = 0; nt < 4; nt++) {
            const int m = wm * 64 + mt * 16 + g;
            const int n = wn * 32 + nt * 8 + 2 * t;
            Cs[m * CSS + n]           = c[mt][nt][0];
            Cs[m * CSS + n + 1]       = c[mt][nt][1];
            Cs[(m + 8) * CSS + n]     = c[mt][nt][2];
            Cs[(m + 8) * CSS + n + 1] = c[mt][nt][3];
        }
    __syncthreads();

    const int part = o0 >> 9;            // 0=q 1=k 2=v
    const int head = (o0 >> 7) & 3;

    if (part == 2) {
#pragma unroll 2
        for (int it = 0; it < 16; it++) {
            const int d = warp + it * 8;
            __half* vr = g_Vt + ((size_t)(b * HEADS + head) * DHEAD + d) * SEQ + p0;
#pragma unroll
            for (int pc = 0; pc < 4; pc++) {
                const int pl = pc * 32 + lane;
                vr[pl] = __float2half(Cs[d * CSS + pl]);
            }
        }
        return;
    }

#pragma unroll 2
    for (int it = 0; it < 16; it++) {
        const int pl = warp + it * 8;
        const int p  = p0 + pl;
        const int xh = p >> 5, yw = p & 31;
        const size_t ob = ((size_t)(b * HEADS + head) * SEQ + p) * DHEAD;
        if (part == 0) {
#pragma unroll
            for (int dc = 0; dc < 4; dc++) {
                const int d = dc * 32 + lane;
                g_Q[ob + d] = __float2half(Cs[d * CSS + pl] * SCALE);
            }
        } else {
#pragma unroll
            for (int dc = 0; dc < 4; dc++) {
                const int d = dc * 32 + lane;
                g_K[ob + d] = __float2half(Cs[d * CSS + pl]
                                           + height[xh * DHEAD + d] + width[yw * DHEAD + d]);
            }
        }
    }
}

// ---------------------------------------------------------------------------
// Kernel 2: flash attention, fp16 mma, 256 threads, 2 CTAs/SM.
// Br=64, Bc=64, 16 j-tiles. No running max. All fragment loads via
// ldmatrix.x4 (4 fragments / instruction; row strides give banks 4i mod 32
// -> conflict-free phases). S: warp = (rowgrp 0..3)x(colhalf 0..1).
// PV: warp = (rowgrp 0..1)x(d-quarter 0..3).
// ---------------------------------------------------------------------------
#define KSH 136
#define VSH 72
#define PSH 72
#define KS0_H 0
#define KS1_H (64 * KSH)
#define VS0_H (2 * 64 * KSH)
#define VS1_H (VS0_H + 128 * VSH)
#define PS_H  (VS1_H + 128 * VSH)
#define LB_B  ((PS_H + 64 * PSH) * 2)    // 80896
#define K2_SMEM (LB_B + 512)             // 81408 B -> 2 CTAs/SM

__global__ __launch_bounds__(256, 2) void attn_mma_kernel(float* __restrict__ out)
{
    extern __shared__ __half smh[];
    const uint32_t smb = smem_u32(smh);
    __half* Ph = smh + PS_H;   // 64 x PSH (CTA-shared)

    const int bh = blockIdx.y;
    const int i0 = blockIdx.x * 64;
    const int tid = threadIdx.x;
    const int warp = tid >> 5, lane = tid & 31;
    const int g = lane >> 2, t = lane & 3;

    const int rw  = warp >> 1;         // S row group (16 rows)
    const int chs = warp & 1;          // S col half (32 cols)
    const int rg  = warp >> 2;         // PV row group (32 rows)
    const int dq  = warp & 3;          // PV d quarter (32 d)
    const int r0 = rg * 32;
    const int dbase = dq * 32;

    const size_t base  = (size_t)bh * SEQ * DHEAD;
    const size_t vbase = (size_t)bh * DHEAD * SEQ;

    // ldmatrix lane-dependent offsets (bytes)
    const int l8  = lane & 7;
    const int lh  = (lane >> 3) & 1;   // k-half selector
    const int lq  = lane >> 4;         // row-block selector
    // K b-frag x4: tiles (rows n0+lq*8+l8, col kc + lh*8); n0 = chs*32 + pair*16
    const uint32_t koff = (uint32_t)(((chs * 32 + lq * 8 + l8) * KSH + lh * 8) * 2);
    // P a-frag x4: tiles (rows rbase + lh*8 + l8, col kc + lq*8)
    const uint32_t poff = (uint32_t)(((lh * 8 + l8) * PSH + lq * 8) * 2);
    const uint32_t pbase_b = smb + PS_H * 2;
    // V b-frag x4: tiles (rows dbase + pair*16 + lq*8 + l8, col kc + lh*8)
    const uint32_t voff = (uint32_t)(((dbase + lq * 8 + l8) * VSH + lh * 8) * 2);

#define ATTN_STAGE(jn) do {                                                        \
        const uint32_t _kb = smb + (((jn) & 1) ? KS1_H : KS0_H) * 2;               \
        const uint32_t _vb = smb + (((jn) & 1) ? VS1_H : VS0_H) * 2;               \
        const __half* _Kg = g_K + base + (size_t)((jn) * 64) * DHEAD;              \
        const __half* _Vg = g_Vt + vbase + (size_t)((jn) * 64);                    \
        _Pragma("unroll")                                                          \
        for (int pass = 0; pass < 4; pass++) {                                     \
            const int id = tid + pass * 256;                                       \
            const int kr = id >> 4, kc8 = (id & 15) * 8;                           \
            CP_ASYNC16(_kb + (uint32_t)(kr * KSH + kc8) * 2,                       \
                       _Kg + (size_t)kr * DHEAD + kc8);                            \
            const int vr = id >> 3, vc8 = (id & 7) * 8;                            \
            CP_ASYNC16(_vb + (uint32_t)(vr * VSH + vc8) * 2,                       \
                       _Vg + (size_t)vr * SEQ + vc8);                              \
        }                                                                          \
        CP_COMMIT();                                                               \
    } while (0)

    ATTN_STAGE(0);

    // Preload Q A-fragments (rows i0 + rw*16 .. +15), 8 k16-steps
    unsigned QA[8][4];
    {
        const __half* Qg = g_Q + base + (size_t)(i0 + rw * 16) * DHEAD;
#pragma unroll
        for (int ks = 0; ks < 8; ks++) {
            QA[ks][0] = U32H(&Qg[g * DHEAD + ks * 16 + 2 * t]);
            QA[ks][1] = U32H(&Qg[(g + 8) * DHEAD + ks * 16 + 2 * t]);
            QA[ks][2] = U32H(&Qg[g * DHEAD + ks * 16 + 2 * t + 8]);
            QA[ks][3] = U32H(&Qg[(g + 8) * DHEAD + ks * 16 + 2 * t + 8]);
        }
    }

    float l_a = 0.0f, l_b = 0.0f;
    float oc[2][4][4];
#pragma unroll
    for (int mt = 0; mt < 2; mt++)
#pragma unroll
        for (int dt = 0; dt < 4; dt++)
#pragma unroll
            for (int i = 0; i < 4; i++) oc[mt][dt][i] = 0.0f;

    for (int jt = 0; jt < 16; jt++) {
        if (jt < 15) ATTN_STAGE(jt + 1);
        if (jt < 15) { CP_WAIT1(); } else { CP_WAIT0(); }
        __syncthreads();

        const uint32_t kb = smb + ((jt & 1) ? KS1_H : KS0_H) * 2 + koff;
        const uint32_t vb = smb + ((jt & 1) ? VS1_H : VS0_H) * 2 + voff;

        // S = Q @ K^T : warp tile 16 x 32; K b-frags via ldmatrix.x4
        float sc[4][4];
#pragma unroll
        for (int nt = 0; nt < 4; nt++)
#pragma unroll
            for (int i = 0; i < 4; i++) sc[nt][i] = 0.0f;

#pragma unroll
        for (int ks = 0; ks < 8; ks++) {
#pragma unroll
            for (int pr = 0; pr < 2; pr++) {   // nt pairs {0,1},{2,3}
                unsigned b0, b1, b2, b3;
                ldsm4(b0, b1, b2, b3, kb + (uint32_t)((pr * 16 * KSH + ks * 16) * 2));
                unsigned bfa[2] = {b0, b1}, bfb[2] = {b2, b3};
                mma16(sc[pr * 2],     QA[ks], bfa);
                mma16(sc[pr * 2 + 1], QA[ks], bfb);
            }
        }

        // exp + partial sums + P store
#pragma unroll
        for (int nt = 0; nt < 4; nt++) {
            const float p0 = __expf(sc[nt][0]);
            const float p1 = __expf(sc[nt][1]);
            const float p2 = __expf(sc[nt][2]);
            const float p3 = __expf(sc[nt][3]);
            l_a += p0 + p1;
            l_b += p2 + p3;
            const int n2 = chs * 32 + nt * 8 + 2 * t;
            *(__half2*)&Ph[(rw * 16 + g) * PSH + n2]     = __floats2half2_rn(p0, p1);
            *(__half2*)&Ph[(rw * 16 + 8 + g) * PSH + n2] = __floats2half2_rn(p2, p3);
        }
        __syncthreads();   // P complete before cross-warp PV reads

        // O += P @ V : a-frags (P) and b-frags (V) via ldmatrix.x4
#pragma unroll
        for (int ks = 0; ks < 4; ks++) {
            const uint32_t kcb = (uint32_t)(ks * 16 * 2);
            unsigned a0[4], a1[4];
            ldsm4(a0[0], a0[1], a0[2], a0[3],
                  pbase_b + poff + (uint32_t)(r0 * PSH * 2) + kcb);
            ldsm4(a1[0], a1[1], a1[2], a1[3],
                  pbase_b + poff + (uint32_t)((r0 + 16) * PSH * 2) + kcb);
#pragma unroll
            for (int pr = 0; pr < 2; pr++) {   // dt pairs {0,1},{2,3}
                unsigned v0, v1, v2, v3;
                ldsm4(v0, v1, v2, v3, vb + (uint32_t)(pr * 16 * VSH * 2) + kcb);
                unsigned bfa[2] = {v0, v1}, bfb[2] = {v2, v3};
                mma16(oc[0][pr * 2],     a0, bfa);
                mma16(oc[0][pr * 2 + 1], a0, bfb);
                mma16(oc[1][pr * 2],     a1, bfa);
                mma16(oc[1][pr * 2 + 1], a1, bfb);
            }
        }
        __syncthreads();   // PV reads done before next tile's P writes / cp.async
    }

    // ---- epilogue ----
    l_a += __shfl_xor_sync(0xffffffffu, l_a, 1);
    l_a += __shfl_xor_sync(0xffffffffu, l_a, 2);
    l_b += __shfl_xor_sync(0xffffffffu, l_b, 1);
    l_b += __shfl_xor_sync(0xffffffffu, l_b, 2);
    float* lbuf = (float*)((char*)smh + LB_B);
    if (t == 0) {
        lbuf[chs * 64 + rw * 16 + g]     = l_a;
        lbuf[chs * 64 + rw * 16 + 8 + g] = l_b;
    }
    __syncthreads();

    float linv[2][2];
#pragma unroll
    for (int mt = 0; mt < 2; mt++) {
        const int ra = r0 + mt * 16 + g;
        linv[mt][0] = 1.0f / (lbuf[ra] + lbuf[64 + ra]);
        linv[mt][1] = 1.0f / (lbuf[ra + 8] + lbuf[64 + ra + 8]);
    }

    // stage O transposed [d][i_local]: 128 x 68 floats (disjoint from lbuf)
    float* Os = (float*)smh;
#pragma unroll
    for (int mt = 0; mt < 2; mt++)
#pragma unroll
        for (int dt = 0; dt < 4; dt++) {
            const int dr = dbase + dt * 8 + 2 * t;
            const int ra = r0 + mt * 16 + g;
            Os[dr * 68 + ra]           = oc[mt][dt][0] * linv[mt][0];
            Os[(dr + 1) * 68 + ra]     = oc[mt][dt][1] * linv[mt][0];
            Os[dr * 68 + ra + 8]       = oc[mt][dt][2] * linv[mt][1];
            Os[(dr + 1) * 68 + ra + 8] = oc[mt][dt][3] * linv[mt][1];
        }
    __syncthreads();

    // coalesced output: lanes 0-15 -> row d, lanes 16-31 -> row d+1 (256B each)
    const int b = bh >> 2, head = bh & 3;
#pragma unroll
    for (int it = 0; it < 8; it++) {
        const int d = warp * 2 + (lane >> 4) + it * 16;
        const int cl = (lane & 15) * 4;
        float4 v = *(const float4*)&Os[d * 68 + cl];
        *(float4*)&out[((size_t)(b * (HEADS * DHEAD) + head * DHEAD + d)) * HW + i0 + cl] = v;
    }
}

// ---------------------------------------------------------------------------
extern "C" void kernel_launch(void* const* d_in, const int* in_sizes, int n_in,
                              void* d_out, int out_size)
{
    const float* fmap   = (const float*)d_in[0];
    const float* w_qkv  = (const float*)d_in[1];
    const float* height = (const float*)d_in[2];
    const float* width  = (const float*)d_in[3];
    float* out = (float*)d_out;

    cudaFuncSetAttribute(qkv_mma_kernel,  cudaFuncAttributeMaxDynamicSharedMemorySize, K1_SMEM);
    cudaFuncSetAttribute(attn_mma_kernel, cudaFuncAttributeMaxDynamicSharedMemorySize, K2_SMEM);

    conv_w_kernel<<<O3 * CHAN / 1024, 256>>>(w_qkv);
    transp_f_kernel<<<dim3(HW / 32, CHAN / 32, BATCH), 256>>>(fmap);
    qkv_mma_kernel<<<dim3(HW / 128, O3 / 128, BATCH), 256, K1_SMEM>>>(height, width);
    attn_mma_kernel<<<dim3(SEQ / 64, BATCH * HEADS), 256, K2_SMEM>>>(out);
}